// round 11
// baseline (speedup 1.0000x reference)
#include <cuda_runtime.h>
#include <cuda_bf16.h>
#include <cstdint>

#define NB   16384
#define RNN  256
#define LAT  64
#define ATT  64
#define NA   32
#define HID  256
#define NF   320   // 256 xh + 32 q + 32 score

// ======================= device globals =======================
__device__ __align__(16) float g_bias[NF];
__device__ __align__(16) __nv_bfloat16 g_Ah[(size_t)NB * RNN];
__device__ __align__(16) __nv_bfloat16 g_Al[(size_t)NB * RNN];
__device__ __align__(16) __nv_bfloat16 g_Bh[RNN * NF];
__device__ __align__(16) __nv_bfloat16 g_Bl[RNN * NF];
__device__ __align__(16) float g_Y[(size_t)NB * NF];          // only cols 256..319 used
__device__ __align__(16) __nv_bfloat16 g_Shi[(size_t)NB * HID]; // S' hi plane
__device__ __align__(16) __nv_bfloat16 g_Slo[(size_t)NB * HID]; // S' lo plane
__device__ __align__(16) float g_t[32 * HID];    // sorted thresholds [rank][h]
__device__ __align__(16) float g_K2[33 * HID];   // const term [rank][h]
__device__ __align__(16) __nv_bfloat16 g_w2h[HID * NA];  // w2^T hi [h][a]
__device__ __align__(16) __nv_bfloat16 g_w2l[HID * NA];  // w2^T lo [h][a]
__device__ __align__(16) float g_msb[NA];        // 32*b2

// ======================= asm helpers =======================
__device__ __forceinline__ uint32_t smem_u32(const void* p) {
    uint32_t a;
    asm("{ .reg .u64 t; cvta.to.shared.u64 t, %1; cvt.u32.u64 %0, t; }" : "=r"(a) : "l"(p));
    return a;
}
__device__ __forceinline__ void cp16(uint32_t dst, const void* src) {
    asm volatile("cp.async.ca.shared.global [%0], [%1], 16;" :: "r"(dst), "l"(src));
}
#define CP_COMMIT asm volatile("cp.async.commit_group;" ::: "memory")
#define CP_WAIT0  asm volatile("cp.async.wait_group 0;" ::: "memory")
#define CP_WAIT1  asm volatile("cp.async.wait_group 1;" ::: "memory")

__device__ __forceinline__ void ldsm_x4(uint32_t* r, uint32_t a) {
    asm volatile("ldmatrix.sync.aligned.m8n8.x4.shared.b16 {%0,%1,%2,%3}, [%4];"
        : "=r"(r[0]), "=r"(r[1]), "=r"(r[2]), "=r"(r[3]) : "r"(a));
}
__device__ __forceinline__ void ldsm_x4t(uint32_t* r, uint32_t a) {
    asm volatile("ldmatrix.sync.aligned.m8n8.x4.trans.shared.b16 {%0,%1,%2,%3}, [%4];"
        : "=r"(r[0]), "=r"(r[1]), "=r"(r[2]), "=r"(r[3]) : "r"(a));
}
__device__ __forceinline__ void mma16816(float* c, const uint32_t* a, const uint32_t* b) {
    asm volatile("mma.sync.aligned.m16n8k16.row.col.f32.bf16.bf16.f32 "
        "{%0,%1,%2,%3}, {%4,%5,%6,%7}, {%8,%9}, {%0,%1,%2,%3};"
        : "+f"(c[0]), "+f"(c[1]), "+f"(c[2]), "+f"(c[3])
        : "r"(a[0]), "r"(a[1]), "r"(a[2]), "r"(a[3]), "r"(b[0]), "r"(b[1]));
}
__device__ __forceinline__ uint32_t pack_bf2(float a, float b, float* ra, float* rb) {
    __nv_bfloat16 ha = __float2bfloat16_rn(a);
    __nv_bfloat16 hb = __float2bfloat16_rn(b);
    *ra = a - __bfloat162float(ha);
    *rb = b - __bfloat162float(hb);
    return (uint32_t)__bfloat16_as_ushort(ha) | ((uint32_t)__bfloat16_as_ushort(hb) << 16);
}

// ======================= K1: prep_w = B-pack/bias (0..319) + sortprep (320..351) =======================
__global__ void __launch_bounds__(256) prep_w_kernel(const float* __restrict__ act,
                                                     const float* __restrict__ qfw,
                                                     const float* __restrict__ qfb,
                                                     const float* __restrict__ w1,
                                                     const float* __restrict__ b1,
                                                     const float* __restrict__ w2,
                                                     const float* __restrict__ b2,
                                                     const float* __restrict__ kw,
                                                     const float* __restrict__ kb,
                                                     const float* __restrict__ qw,
                                                     const float* __restrict__ qb) {
    int tid = threadIdx.x;
    if (blockIdx.x < 320) {
        __shared__ float s_act[LAT];
        __shared__ float s_q[ATT];
        int j = blockIdx.x, k = tid;
        float v;
        if (j < 256) {
            v = w1[j * (RNN + LAT) + k];
        } else if (j < 288) {
            int a = j - 256;
            if (tid < LAT) s_act[tid] = act[a * LAT + tid];
            __syncthreads();
            v = 0.f;
#pragma unroll 8
            for (int l = 0; l < LAT; l++) v += s_act[l] * qfw[l * RNN + k];
        } else {
            int a = j - 288;
            if (tid < LAT) s_act[tid] = act[a * LAT + tid];
            __syncthreads();
            if (tid < ATT) {
                float q = qb[tid];
#pragma unroll 8
                for (int l = 0; l < LAT; l++) q += s_act[l] * qw[tid * LAT + l];
                s_q[tid] = q;
            }
            __syncthreads();
            v = 0.f;
#pragma unroll 8
            for (int t = 0; t < ATT; t++) v += s_q[t] * kw[t * RNN + k];
            v *= 0.125f;
        }
        __nv_bfloat16 hb = __float2bfloat16_rn(v);
        g_Bh[k * NF + j] = hb;
        g_Bl[k * NF + j] = __float2bfloat16_rn(v - __bfloat162float(hb));
        if (tid == 0) {
            float b = 0.f;
            if (j >= 256 && j < 288) {
                for (int l = 0; l < LAT; l++) b += s_act[l] * qfb[l];
            } else if (j >= 288) {
                for (int t = 0; t < ATT; t++) b += s_q[t] * kb[t];
                b *= 0.125f;
            }
            g_bias[j] = b;
        }
    } else {
        // -------- sortprep: ya, branchless rank sort, prefix, w2 bf16 pack --------
        __shared__ float s_actT[LAT * NA];
        __shared__ float s_v[8][NA];
        __shared__ float s_d[8][NA];
        int w = tid >> 5, lane = tid & 31;
        for (int i = tid; i < NA * LAT; i += 256) {
            int a = i >> 6, l = i & 63;
            s_actT[l * NA + a] = act[i];
        }
        __syncthreads();

        int hcol = (blockIdx.x - 320) * 8 + w;
        float val = b1[hcol];
#pragma unroll 8
        for (int l = 0; l < LAT; l++)
            val = fmaf(s_actT[l * NA + lane], w1[hcol * (RNN + LAT) + RNN + l], val);
        s_v[w][lane] = val;
        __syncwarp();
        int rank = 0;
#pragma unroll
        for (int b = 0; b < NA; b++) {
            float o = s_v[w][b];
            rank += (o > val) || (o == val && b < lane);
        }
        s_d[w][rank] = val;
        __syncwarp();
        float sv = s_d[w][lane];
        float incl = sv;
#pragma unroll
        for (int o = 1; o < 32; o <<= 1) {
            float u = __shfl_up_sync(0xffffffffu, incl, o);
            if (lane >= o) incl += u;
        }
        float excl = incl - sv;
        float ytot = __shfl_sync(0xffffffffu, incl, 31);
        g_t[lane * HID + hcol]  = -sv;
        g_K2[lane * HID + hcol] = fmaf(0.99f, excl, 0.01f * ytot);
        if (lane == 0) g_K2[32 * HID + hcol] = ytot;
        float wv = w2[lane * HID + hcol];
        __nv_bfloat16 wh = __float2bfloat16_rn(wv);
        g_w2h[hcol * NA + lane] = wh;
        g_w2l[hcol * NA + lane] = __float2bfloat16_rn(wv - __bfloat162float(wh));
        if (blockIdx.x == 320 && w == 0) g_msb[lane] = 32.f * b2[lane];
    }
}

// ======================= K2: prep_a = A-pack with 2-chunk ILP =======================
#define APACK_HALF (NB * RNN / 8 / 2)   // 262144 chunks per half

__global__ void __launch_bounds__(256) prep_a_kernel(const float* __restrict__ h) {
    int u0 = blockIdx.x * 256 + threadIdx.x;   // chunk in first half
#pragma unroll
    for (int half = 0; half < 2; half++) {
        int u = u0 + half * APACK_HALF;
        int b = u >> 5;
        int k0 = (u & 31) * 8;
        float4 v0 = *(const float4*)&h[(size_t)b * RNN + k0];
        float4 v1 = *(const float4*)&h[(size_t)b * RNN + k0 + 4];
        float v[8] = {v0.x, v0.y, v0.z, v0.w, v1.x, v1.y, v1.z, v1.w};
        uint32_t hw[4], lw[4];
#pragma unroll
        for (int i = 0; i < 4; i++) {
            float a = v[2 * i], bb = v[2 * i + 1];
            __nv_bfloat16 ha = __float2bfloat16_rn(a);
            __nv_bfloat16 hb = __float2bfloat16_rn(bb);
            __nv_bfloat16 la = __float2bfloat16_rn(a - __bfloat162float(ha));
            __nv_bfloat16 lb = __float2bfloat16_rn(bb - __bfloat162float(hb));
            hw[i] = (uint32_t)__bfloat16_as_ushort(ha) | ((uint32_t)__bfloat16_as_ushort(hb) << 16);
            lw[i] = (uint32_t)__bfloat16_as_ushort(la) | ((uint32_t)__bfloat16_as_ushort(lb) << 16);
        }
        size_t off = (size_t)b * RNN + k0;
        *(uint4*)&g_Ah[off] = make_uint4(hw[0], hw[1], hw[2], hw[3]);
        *(uint4*)&g_Al[off] = make_uint4(lw[0], lw[1], lw[2], lw[3]);
    }
}

// ======================= K3: HMMA GEMM + fused leaky epilogue (bf16 S' out) =======================
#define A_H  0
#define A_L  10240
#define B_H  20480
#define B_L  25088
#define BUFB 29696
#define TSTR 65
#define SM_T   (2 * BUFB)
#define SM_K2  (SM_T + 32 * TSTR * 4)
#define GEMM_SMEM (SM_K2 + 33 * TSTR * 4)

__global__ void __launch_bounds__(256, 2) gemm_mma_kernel() {
    extern __shared__ char gsm[];
    uint32_t sb = smem_u32(gsm);
    int tid = threadIdx.x;
    int lane = tid & 31, wid = tid >> 5;
    int wm = wid & 3, wn = wid >> 2;
    int m0 = blockIdx.y * 128;
    int n0 = blockIdx.x * 64;
    bool leakyBlk = (n0 < 256);

    if (leakyBlk) {
        float* st = (float*)(gsm + SM_T);
        float* sk = (float*)(gsm + SM_K2);
        for (int i = tid; i < 32 * 64; i += 256)
            st[(i >> 6) * TSTR + (i & 63)] = g_t[(i >> 6) * HID + n0 + (i & 63)];
        for (int i = tid; i < 33 * 64; i += 256)
            sk[(i >> 6) * TSTR + (i & 63)] = g_K2[(i >> 6) * HID + n0 + (i & 63)];
    }

    float acc[2][4][4];
#pragma unroll
    for (int mt = 0; mt < 2; mt++)
#pragma unroll
        for (int nt = 0; nt < 4; nt++)
#pragma unroll
            for (int i = 0; i < 4; i++) acc[mt][nt][i] = 0.f;

    auto load_tiles = [&](int it, int buf) {
        int k0 = it * 32;
        uint32_t base = sb + buf * BUFB;
#pragma unroll
        for (int i = 0; i < 2; i++) {
            int c = tid + 256 * i;
            int row = c >> 2, ch = c & 3;
            size_t src = (size_t)(m0 + row) * RNN + k0 + ch * 8;
            cp16(base + A_H + row * 80 + ch * 16, g_Ah + src);
            cp16(base + A_L + row * 80 + ch * 16, g_Al + src);
        }
        {
            int row = tid >> 3, ch = tid & 7;
            size_t src = (size_t)(k0 + row) * NF + n0 + ch * 8;
            cp16(base + B_H + row * 144 + ch * 16, g_Bh + src);
            cp16(base + B_L + row * 144 + ch * 16, g_Bl + src);
        }
    };

    auto compute = [&](int buf) {
        uint32_t base = sb + buf * BUFB;
#pragma unroll
        for (int ks = 0; ks < 32; ks += 16) {
            uint32_t ah[2][4], al[2][4], bh[2][4], bl[2][4];
            int arow = (lane & 7) + ((lane >> 3) & 1) * 8;
            int akk = ks + (lane >> 4) * 8;
#pragma unroll
            for (int mt = 0; mt < 2; mt++) {
                uint32_t ao = (wm * 32 + mt * 16 + arow) * 80 + akk * 2;
                ldsm_x4(ah[mt], base + A_H + ao);
                ldsm_x4(al[mt], base + A_L + ao);
            }
            int bk = ks + (lane & 7) + ((lane >> 3) & 1) * 8;
#pragma unroll
            for (int np = 0; np < 2; np++) {
                int bn = wn * 32 + np * 16 + ((lane >> 4) & 1) * 8;
                uint32_t bo = bk * 144 + bn * 2;
                ldsm_x4t(bh[np], base + B_H + bo);
                ldsm_x4t(bl[np], base + B_L + bo);
            }
#pragma unroll
            for (int mt = 0; mt < 2; mt++)
#pragma unroll
                for (int nt = 0; nt < 4; nt++) {
                    int np = nt >> 1, hf = nt & 1;
                    mma16816(acc[mt][nt], ah[mt], &bh[np][hf * 2]);
                    mma16816(acc[mt][nt], al[mt], &bh[np][hf * 2]);
                    mma16816(acc[mt][nt], ah[mt], &bl[np][hf * 2]);
                }
        }
    };

    load_tiles(0, 0);
    CP_COMMIT;
    for (int it = 0; it < 8; it++) {
        if (it + 1 < 8) { load_tiles(it + 1, (it + 1) & 1); CP_COMMIT; CP_WAIT1; }
        else            { CP_WAIT0; }
        __syncthreads();
        compute(it & 1);
        __syncthreads();
    }

    if (leakyBlk) {
        const float* st = (const float*)(gsm + SM_T);
        const float* sk = (const float*)(gsm + SM_K2);
#pragma unroll
        for (int mt = 0; mt < 2; mt++) {
            int row = m0 + wm * 32 + mt * 16 + (lane >> 2);
#pragma unroll
            for (int nt = 0; nt < 4; nt++) {
                int cl0 = wn * 32 + nt * 8 + (lane & 3) * 2;
                float xs[4] = {acc[mt][nt][0], acc[mt][nt][1], acc[mt][nt][2], acc[mt][nt][3]};
                int cc[4] = {cl0, cl0 + 1, cl0, cl0 + 1};
                int lo[4] = {0, 0, 0, 0};
#pragma unroll
                for (int bb = 16; bb >= 1; bb >>= 1)
#pragma unroll
                    for (int v = 0; v < 4; v++)
                        lo[v] += (xs[v] >= st[(lo[v] + bb - 1) * TSTR + cc[v]]) ? bb : 0;
#pragma unroll
                for (int v = 0; v < 4; v++)
                    lo[v] += (xs[v] >= st[lo[v] * TSTR + cc[v]]) ? 1 : 0;
                float sp[4];
#pragma unroll
                for (int v = 0; v < 4; v++)
                    sp[v] = fmaf(xs[v], fmaf((float)lo[v], 0.99f, 0.32f), sk[lo[v] * TSTR + cc[v]]);
                int gc = n0 + cl0;
                float r0, r1, r2, r3;
                uint32_t hi01 = pack_bf2(sp[0], sp[1], &r0, &r1);
                uint32_t hi23 = pack_bf2(sp[2], sp[3], &r2, &r3);
                uint32_t lo01 = pack_bf2(r0, r1, &r0, &r1);
                uint32_t lo23 = pack_bf2(r2, r3, &r2, &r3);
                *(uint32_t*)&g_Shi[(size_t)row * HID + gc]       = hi01;
                *(uint32_t*)&g_Slo[(size_t)row * HID + gc]       = lo01;
                *(uint32_t*)&g_Shi[(size_t)(row + 8) * HID + gc] = hi23;
                *(uint32_t*)&g_Slo[(size_t)(row + 8) * HID + gc] = lo23;
            }
        }
    } else {
#pragma unroll
        for (int mt = 0; mt < 2; mt++) {
            int row = m0 + wm * 32 + mt * 16 + (lane >> 2);
#pragma unroll
            for (int nt = 0; nt < 4; nt++) {
                int col = n0 + wn * 32 + nt * 8 + (lane & 3) * 2;
                float bx = g_bias[col], by = g_bias[col + 1];
                float2 o0 = make_float2(acc[mt][nt][0] + bx, acc[mt][nt][1] + by);
                float2 o1 = make_float2(acc[mt][nt][2] + bx, acc[mt][nt][3] + by);
                *(float2*)&g_Y[(size_t)row * NF + col] = o0;
                *(float2*)&g_Y[(size_t)(row + 8) * NF + col] = o1;
            }
        }
    }
}

// ======================= K4: combine (BM=64, 128 thr) = HMMA msg GEMM + softmax =======================
#define C_BUF 10240             // per A buffer: hi 5120 + lo 5120
#define C_BH  20480             // B hi plane: 256 rows * 80B = 20480
#define C_BL  (C_BH + 20480)
#define COMB_SMEM (C_BL + 20480)

__global__ void __launch_bounds__(128, 2) combine_kernel(float* __restrict__ out) {
    extern __shared__ char csm[];
    uint32_t sb = smem_u32(csm);
    __shared__ float s_msb[NA];
    int tid = threadIdx.x, lane = tid & 31, wid = tid >> 5;  // 4 warps
    int m0 = blockIdx.x * 64;
    if (tid < NA) s_msb[tid] = g_msb[tid];

    // resident B preload (w2^T hi/lo), 256 rows, 64B payload @80B stride
    for (int i = tid; i < 1024; i += 128) {
        int row = i >> 2, ch = i & 3;
        cp16(sb + C_BH + row * 80 + ch * 16, g_w2h + row * 32 + ch * 8);
        cp16(sb + C_BL + row * 80 + ch * 16, g_w2l + row * 32 + ch * 8);
    }

    auto loadA = [&](int c, int buf) {
        int k0 = c * 32;
        uint32_t base = sb + buf * C_BUF;
#pragma unroll
        for (int i = tid; i < 256; i += 128) {
            int row = i >> 2, ch = i & 3;
            size_t src = (size_t)(m0 + row) * HID + k0 + ch * 8;
            cp16(base + row * 80 + ch * 16, g_Shi + src);
            cp16(base + 5120 + row * 80 + ch * 16, g_Slo + src);
        }
    };

    float acc[4][4];
#pragma unroll
    for (int nt = 0; nt < 4; nt++)
#pragma unroll
        for (int i = 0; i < 4; i++) acc[nt][i] = 0.f;

    loadA(0, 0);
    CP_COMMIT;
    for (int c = 0; c < 8; c++) {
        if (c + 1 < 8) { loadA(c + 1, (c + 1) & 1); CP_COMMIT; CP_WAIT1; }
        else           { CP_WAIT0; }
        __syncthreads();
        uint32_t abase = sb + (c & 1) * C_BUF;
#pragma unroll
        for (int ks = 0; ks < 32; ks += 16) {
            uint32_t ah[4], al[4], bh[2][4], bl[2][4];
            int arow = (lane & 7) + ((lane >> 3) & 1) * 8;
            int akk = ks + (lane >> 4) * 8;
            uint32_t ao = (wid * 16 + arow) * 80 + akk * 2;
            ldsm_x4(ah, abase + ao);
            ldsm_x4(al, abase + 5120 + ao);
            int bkg = c * 32 + ks + (lane & 7) + ((lane >> 3) & 1) * 8;
#pragma unroll
            for (int np = 0; np < 2; np++) {
                int bn = np * 16 + ((lane >> 4) & 1) * 8;
                uint32_t bo = bkg * 80 + bn * 2;
                ldsm_x4t(bh[np], sb + C_BH + bo);
                ldsm_x4t(bl[np], sb + C_BL + bo);
            }
#pragma unroll
            for (int nt = 0; nt < 4; nt++) {
                int np = nt >> 1, hf = nt & 1;
                mma16816(acc[nt], ah, &bh[np][hf * 2]);
                mma16816(acc[nt], al, &bh[np][hf * 2]);
                mma16816(acc[nt], ah, &bl[np][hf * 2]);
            }
        }
        __syncthreads();
    }

    // in-fragment softmax + combine (warp owns 16 rows x all 32 actions)
    int rbase = m0 + wid * 16 + (lane >> 2);
#pragma unroll
    for (int half = 0; half < 2; half++) {
        int row = rbase + half * 8;
        const float* Yr = g_Y + (size_t)row * NF;
        float qv[8], sc[8], mv[8];
#pragma unroll
        for (int nt = 0; nt < 4; nt++) {
            int col = nt * 8 + (lane & 3) * 2;
            float2 q2 = *(const float2*)&Yr[256 + col];
            float2 s2 = *(const float2*)&Yr[288 + col];
            qv[nt * 2] = q2.x; qv[nt * 2 + 1] = q2.y;
            sc[nt * 2] = s2.x; sc[nt * 2 + 1] = s2.y;
            mv[nt * 2]     = acc[nt][half * 2 + 0] + s_msb[col];
            mv[nt * 2 + 1] = acc[nt][half * 2 + 1] + s_msb[col + 1];
        }
        float mx = sc[0];
#pragma unroll
        for (int i = 1; i < 8; i++) mx = fmaxf(mx, sc[i]);
        mx = fmaxf(mx, __shfl_xor_sync(0xffffffffu, mx, 1));
        mx = fmaxf(mx, __shfl_xor_sync(0xffffffffu, mx, 2));
        float e[8], se = 0.f;
#pragma unroll
        for (int i = 0; i < 8; i++) { e[i] = __expf(sc[i] - mx); se += e[i]; }
        se += __shfl_xor_sync(0xffffffffu, se, 1);
        se += __shfl_xor_sync(0xffffffffu, se, 2);
        float inv = 1.f / se;
#pragma unroll
        for (int nt = 0; nt < 4; nt++) {
            int col = nt * 8 + (lane & 3) * 2;
            float2 o;
            o.x = qv[nt * 2]     + e[nt * 2]     * inv * mv[nt * 2];
            o.y = qv[nt * 2 + 1] + e[nt * 2 + 1] * inv * mv[nt * 2 + 1];
            *(float2*)&out[(size_t)row * NA + col] = o;
        }
    }
}

// ======================= launch =======================
extern "C" void kernel_launch(void* const* d_in, const int* in_sizes, int n_in,
                              void* d_out, int out_size) {
    const float* h   = (const float*)d_in[0];
    const float* act = (const float*)d_in[1];
    const float* qfw = (const float*)d_in[2];
    const float* qfb = (const float*)d_in[3];
    const float* w1  = (const float*)d_in[4];
    const float* b1  = (const float*)d_in[5];
    const float* w2  = (const float*)d_in[6];
    const float* b2  = (const float*)d_in[7];
    const float* kw  = (const float*)d_in[8];
    const float* kb  = (const float*)d_in[9];
    const float* qw  = (const float*)d_in[10];
    const float* qb  = (const float*)d_in[11];
    float* out = (float*)d_out;
    (void)in_sizes; (void)n_in; (void)out_size;

    cudaFuncSetAttribute(gemm_mma_kernel, cudaFuncAttributeMaxDynamicSharedMemorySize, GEMM_SMEM);
    cudaFuncSetAttribute(combine_kernel,  cudaFuncAttributeMaxDynamicSharedMemorySize, COMB_SMEM);

    prep_w_kernel<<<352, 256>>>(act, qfw, qfb, w1, b1, w2, b2, kw, kb, qw, qb);  // #0
    prep_a_kernel<<<APACK_HALF / 256, 256>>>(h);                                  // #1
    dim3 ggrid(NF / 64, NB / 128);
    gemm_mma_kernel<<<ggrid, 256, GEMM_SMEM>>>();                                 // #2
    combine_kernel<<<NB / 64, 128, COMB_SMEM>>>(out);                             // #3 (profiled)
}

// round 13
// speedup vs baseline: 1.0680x; 1.0680x over previous
#include <cuda_runtime.h>
#include <cuda_bf16.h>
#include <cstdint>

#define NB   16384
#define RNN  256
#define LAT  64
#define ATT  64
#define NA   32
#define HID  256
#define NF   320   // 256 xh + 32 q + 32 score

// ======================= device globals =======================
__device__ __align__(16) float g_bias[NF];
__device__ __align__(16) __nv_bfloat16 g_Ah[(size_t)NB * RNN];
__device__ __align__(16) __nv_bfloat16 g_Al[(size_t)NB * RNN];
__device__ __align__(16) __nv_bfloat16 g_Bh[RNN * NF];
__device__ __align__(16) __nv_bfloat16 g_Bl[RNN * NF];
__device__ __align__(16) float g_Y[(size_t)NB * NF];          // only cols 256..319 used
__device__ __align__(16) __nv_bfloat16 g_Shi[(size_t)NB * HID]; // S' hi plane
__device__ __align__(16) __nv_bfloat16 g_Slo[(size_t)NB * HID]; // S' lo plane
__device__ __align__(16) float g_t[32 * HID];    // sorted thresholds [rank][h]
__device__ __align__(16) float g_K2[33 * HID];   // const term [rank][h]
__device__ __align__(16) __nv_bfloat16 g_w2h[HID * NA];  // w2^T hi [h][a]
__device__ __align__(16) __nv_bfloat16 g_w2l[HID * NA];  // w2^T lo [h][a]
__device__ __align__(16) float g_msb[NA];        // 32*b2

// ======================= asm helpers =======================
__device__ __forceinline__ uint32_t smem_u32(const void* p) {
    uint32_t a;
    asm("{ .reg .u64 t; cvta.to.shared.u64 t, %1; cvt.u32.u64 %0, t; }" : "=r"(a) : "l"(p));
    return a;
}
__device__ __forceinline__ void cp16(uint32_t dst, const void* src) {
    asm volatile("cp.async.ca.shared.global [%0], [%1], 16;" :: "r"(dst), "l"(src));
}
#define CP_COMMIT asm volatile("cp.async.commit_group;" ::: "memory")
#define CP_WAIT0  asm volatile("cp.async.wait_group 0;" ::: "memory")
#define CP_WAIT1  asm volatile("cp.async.wait_group 1;" ::: "memory")
#define CP_WAIT2  asm volatile("cp.async.wait_group 2;" ::: "memory")

__device__ __forceinline__ void ldsm_x4(uint32_t* r, uint32_t a) {
    asm volatile("ldmatrix.sync.aligned.m8n8.x4.shared.b16 {%0,%1,%2,%3}, [%4];"
        : "=r"(r[0]), "=r"(r[1]), "=r"(r[2]), "=r"(r[3]) : "r"(a));
}
__device__ __forceinline__ void ldsm_x4t(uint32_t* r, uint32_t a) {
    asm volatile("ldmatrix.sync.aligned.m8n8.x4.trans.shared.b16 {%0,%1,%2,%3}, [%4];"
        : "=r"(r[0]), "=r"(r[1]), "=r"(r[2]), "=r"(r[3]) : "r"(a));
}
__device__ __forceinline__ void mma16816(float* c, const uint32_t* a, const uint32_t* b) {
    asm volatile("mma.sync.aligned.m16n8k16.row.col.f32.bf16.bf16.f32 "
        "{%0,%1,%2,%3}, {%4,%5,%6,%7}, {%8,%9}, {%0,%1,%2,%3};"
        : "+f"(c[0]), "+f"(c[1]), "+f"(c[2]), "+f"(c[3])
        : "r"(a[0]), "r"(a[1]), "r"(a[2]), "r"(a[3]), "r"(b[0]), "r"(b[1]));
}
__device__ __forceinline__ uint32_t pack_bf2(float a, float b, float* ra, float* rb) {
    __nv_bfloat16 ha = __float2bfloat16_rn(a);
    __nv_bfloat16 hb = __float2bfloat16_rn(b);
    *ra = a - __bfloat162float(ha);
    *rb = b - __bfloat162float(hb);
    return (uint32_t)__bfloat16_as_ushort(ha) | ((uint32_t)__bfloat16_as_ushort(hb) << 16);
}

// ======================= K1: prep = B-pack/bias | sortprep | A-pack(ILP2) =======================
#define APACK_HALF (NB * RNN / 8 / 2)   // 262144 chunks per half

__global__ void __launch_bounds__(256) prep_kernel(const float* __restrict__ h,
                                                   const float* __restrict__ act,
                                                   const float* __restrict__ qfw,
                                                   const float* __restrict__ qfb,
                                                   const float* __restrict__ w1,
                                                   const float* __restrict__ b1,
                                                   const float* __restrict__ w2,
                                                   const float* __restrict__ b2,
                                                   const float* __restrict__ kw,
                                                   const float* __restrict__ kb,
                                                   const float* __restrict__ qw,
                                                   const float* __restrict__ qb) {
    int tid = threadIdx.x;
    if (blockIdx.x < 320) {
        __shared__ float s_act[LAT];
        __shared__ float s_q[ATT];
        int j = blockIdx.x, k = tid;
        float v;
        if (j < 256) {
            v = w1[j * (RNN + LAT) + k];
        } else if (j < 288) {
            int a = j - 256;
            if (tid < LAT) s_act[tid] = act[a * LAT + tid];
            __syncthreads();
            v = 0.f;
#pragma unroll 8
            for (int l = 0; l < LAT; l++) v += s_act[l] * qfw[l * RNN + k];
        } else {
            int a = j - 288;
            if (tid < LAT) s_act[tid] = act[a * LAT + tid];
            __syncthreads();
            if (tid < ATT) {
                float q = qb[tid];
#pragma unroll 8
                for (int l = 0; l < LAT; l++) q += s_act[l] * qw[tid * LAT + l];
                s_q[tid] = q;
            }
            __syncthreads();
            v = 0.f;
#pragma unroll 8
            for (int t = 0; t < ATT; t++) v += s_q[t] * kw[t * RNN + k];
            v *= 0.125f;
        }
        __nv_bfloat16 hb = __float2bfloat16_rn(v);
        g_Bh[k * NF + j] = hb;
        g_Bl[k * NF + j] = __float2bfloat16_rn(v - __bfloat162float(hb));
        if (tid == 0) {
            float b = 0.f;
            if (j >= 256 && j < 288) {
                for (int l = 0; l < LAT; l++) b += s_act[l] * qfb[l];
            } else if (j >= 288) {
                for (int t = 0; t < ATT; t++) b += s_q[t] * kb[t];
                b *= 0.125f;
            }
            g_bias[j] = b;
        }
    } else if (blockIdx.x < 352) {
        // -------- sortprep --------
        __shared__ float s_actT[LAT * NA];
        __shared__ float s_v[8][NA];
        __shared__ float s_d[8][NA];
        int w = tid >> 5, lane = tid & 31;
        for (int i = tid; i < NA * LAT; i += 256) {
            int a = i >> 6, l = i & 63;
            s_actT[l * NA + a] = act[i];
        }
        __syncthreads();

        int hcol = (blockIdx.x - 320) * 8 + w;
        float val = b1[hcol];
#pragma unroll 8
        for (int l = 0; l < LAT; l++)
            val = fmaf(s_actT[l * NA + lane], w1[hcol * (RNN + LAT) + RNN + l], val);
        s_v[w][lane] = val;
        __syncwarp();
        int rank = 0;
#pragma unroll
        for (int b = 0; b < NA; b++) {
            float o = s_v[w][b];
            rank += (o > val) || (o == val && b < lane);
        }
        s_d[w][rank] = val;
        __syncwarp();
        float sv = s_d[w][lane];
        float incl = sv;
#pragma unroll
        for (int o = 1; o < 32; o <<= 1) {
            float u = __shfl_up_sync(0xffffffffu, incl, o);
            if (lane >= o) incl += u;
        }
        float excl = incl - sv;
        float ytot = __shfl_sync(0xffffffffu, incl, 31);
        g_t[lane * HID + hcol]  = -sv;
        g_K2[lane * HID + hcol] = fmaf(0.99f, excl, 0.01f * ytot);
        if (lane == 0) g_K2[32 * HID + hcol] = ytot;
        float wv = w2[lane * HID + hcol];
        __nv_bfloat16 wh = __float2bfloat16_rn(wv);
        g_w2h[hcol * NA + lane] = wh;
        g_w2l[hcol * NA + lane] = __float2bfloat16_rn(wv - __bfloat162float(wh));
        if (blockIdx.x == 320 && w == 0) g_msb[lane] = 32.f * b2[lane];
    } else {
        // -------- A-pack, 2 independent chunks per thread --------
        int u0 = (blockIdx.x - 352) * 256 + tid;
#pragma unroll
        for (int half = 0; half < 2; half++) {
            int u = u0 + half * APACK_HALF;
            int b = u >> 5;
            int k0 = (u & 31) * 8;
            float4 v0 = *(const float4*)&h[(size_t)b * RNN + k0];
            float4 v1 = *(const float4*)&h[(size_t)b * RNN + k0 + 4];
            float v[8] = {v0.x, v0.y, v0.z, v0.w, v1.x, v1.y, v1.z, v1.w};
            uint32_t hw[4], lw[4];
#pragma unroll
            for (int i = 0; i < 4; i++) {
                float a = v[2 * i], bb = v[2 * i + 1];
                __nv_bfloat16 ha = __float2bfloat16_rn(a);
                __nv_bfloat16 hb = __float2bfloat16_rn(bb);
                __nv_bfloat16 la = __float2bfloat16_rn(a - __bfloat162float(ha));
                __nv_bfloat16 lb = __float2bfloat16_rn(bb - __bfloat162float(hb));
                hw[i] = (uint32_t)__bfloat16_as_ushort(ha) | ((uint32_t)__bfloat16_as_ushort(hb) << 16);
                lw[i] = (uint32_t)__bfloat16_as_ushort(la) | ((uint32_t)__bfloat16_as_ushort(lb) << 16);
            }
            size_t off = (size_t)b * RNN + k0;
            *(uint4*)&g_Ah[off] = make_uint4(hw[0], hw[1], hw[2], hw[3]);
            *(uint4*)&g_Al[off] = make_uint4(lw[0], lw[1], lw[2], lw[3]);
        }
    }
}

// ======================= K2: HMMA GEMM (3-stage pipeline) + fused leaky epilogue =======================
#define A_H  0
#define A_L  10240
#define B_H  20480
#define B_L  25088
#define BUFB 29696
#define TSTR 65
#define SM_T   (3 * BUFB)
#define SM_K2  (SM_T + 32 * TSTR * 4)
#define GEMM_SMEM (SM_K2 + 33 * TSTR * 4)

__global__ void __launch_bounds__(256, 2) gemm_mma_kernel() {
    extern __shared__ char gsm[];
    uint32_t sb = smem_u32(gsm);
    int tid = threadIdx.x;
    int lane = tid & 31, wid = tid >> 5;
    int wm = wid & 3, wn = wid >> 2;
    int m0 = blockIdx.y * 128;
    int n0 = blockIdx.x * 64;
    bool leakyBlk = (n0 < 256);

    if (leakyBlk) {
        float* st = (float*)(gsm + SM_T);
        float* sk = (float*)(gsm + SM_K2);
        for (int i = tid; i < 32 * 64; i += 256)
            st[(i >> 6) * TSTR + (i & 63)] = g_t[(i >> 6) * HID + n0 + (i & 63)];
        for (int i = tid; i < 33 * 64; i += 256)
            sk[(i >> 6) * TSTR + (i & 63)] = g_K2[(i >> 6) * HID + n0 + (i & 63)];
    }

    float acc[2][4][4];
#pragma unroll
    for (int mt = 0; mt < 2; mt++)
#pragma unroll
        for (int nt = 0; nt < 4; nt++)
#pragma unroll
            for (int i = 0; i < 4; i++) acc[mt][nt][i] = 0.f;

    auto load_tiles = [&](int it, int buf) {
        int k0 = it * 32;
        uint32_t base = sb + buf * BUFB;
#pragma unroll
        for (int i = 0; i < 2; i++) {
            int c = tid + 256 * i;
            int row = c >> 2, ch = c & 3;
            size_t src = (size_t)(m0 + row) * RNN + k0 + ch * 8;
            cp16(base + A_H + row * 80 + ch * 16, g_Ah + src);
            cp16(base + A_L + row * 80 + ch * 16, g_Al + src);
        }
        {
            int row = tid >> 3, ch = tid & 7;
            size_t src = (size_t)(k0 + row) * NF + n0 + ch * 8;
            cp16(base + B_H + row * 144 + ch * 16, g_Bh + src);
            cp16(base + B_L + row * 144 + ch * 16, g_Bl + src);
        }
    };

    auto compute = [&](int buf) {
        uint32_t base = sb + buf * BUFB;
#pragma unroll
        for (int ks = 0; ks < 32; ks += 16) {
            uint32_t ah[2][4], al[2][4], bh[2][4], bl[2][4];
            int arow = (lane & 7) + ((lane >> 3) & 1) * 8;
            int akk = ks + (lane >> 4) * 8;
#pragma unroll
            for (int mt = 0; mt < 2; mt++) {
                uint32_t ao = (wm * 32 + mt * 16 + arow) * 80 + akk * 2;
                ldsm_x4(ah[mt], base + A_H + ao);
                ldsm_x4(al[mt], base + A_L + ao);
            }
            int bk = ks + (lane & 7) + ((lane >> 3) & 1) * 8;
#pragma unroll
            for (int np = 0; np < 2; np++) {
                int bn = wn * 32 + np * 16 + ((lane >> 4) & 1) * 8;
                uint32_t bo = bk * 144 + bn * 2;
                ldsm_x4t(bh[np], base + B_H + bo);
                ldsm_x4t(bl[np], base + B_L + bo);
            }
#pragma unroll
            for (int mt = 0; mt < 2; mt++)
#pragma unroll
                for (int nt = 0; nt < 4; nt++) {
                    int np = nt >> 1, hf = nt & 1;
                    mma16816(acc[mt][nt], ah[mt], &bh[np][hf * 2]);
                    mma16816(acc[mt][nt], al[mt], &bh[np][hf * 2]);
                    mma16816(acc[mt][nt], ah[mt], &bl[np][hf * 2]);
                }
        }
    };

    load_tiles(0, 0);
    CP_COMMIT;
    load_tiles(1, 1);
    CP_COMMIT;
    for (int it = 0; it < 8; it++) {
        if (it + 2 < 8)      { load_tiles(it + 2, (it + 2) % 3); CP_COMMIT; CP_WAIT2; }
        else if (it + 1 < 8) { CP_WAIT1; }
        else                 { CP_WAIT0; }
        __syncthreads();
        compute(it % 3);
        __syncthreads();
    }

    if (leakyBlk) {
        const float* st = (const float*)(gsm + SM_T);
        const float* sk = (const float*)(gsm + SM_K2);
#pragma unroll
        for (int mt = 0; mt < 2; mt++) {
            int row = m0 + wm * 32 + mt * 16 + (lane >> 2);
#pragma unroll
            for (int nt = 0; nt < 4; nt++) {
                int cl0 = wn * 32 + nt * 8 + (lane & 3) * 2;
                float xs[4] = {acc[mt][nt][0], acc[mt][nt][1], acc[mt][nt][2], acc[mt][nt][3]};
                int cc[4] = {cl0, cl0 + 1, cl0, cl0 + 1};
                int lo[4] = {0, 0, 0, 0};
#pragma unroll
                for (int bb = 16; bb >= 1; bb >>= 1)
#pragma unroll
                    for (int v = 0; v < 4; v++)
                        lo[v] += (xs[v] >= st[(lo[v] + bb - 1) * TSTR + cc[v]]) ? bb : 0;
#pragma unroll
                for (int v = 0; v < 4; v++)
                    lo[v] += (xs[v] >= st[lo[v] * TSTR + cc[v]]) ? 1 : 0;
                float sp[4];
#pragma unroll
                for (int v = 0; v < 4; v++)
                    sp[v] = fmaf(xs[v], fmaf((float)lo[v], 0.99f, 0.32f), sk[lo[v] * TSTR + cc[v]]);
                int gc = n0 + cl0;
                float r0, r1, r2, r3;
                uint32_t hi01 = pack_bf2(sp[0], sp[1], &r0, &r1);
                uint32_t hi23 = pack_bf2(sp[2], sp[3], &r2, &r3);
                uint32_t lo01 = pack_bf2(r0, r1, &r0, &r1);
                uint32_t lo23 = pack_bf2(r2, r3, &r2, &r3);
                *(uint32_t*)&g_Shi[(size_t)row * HID + gc]       = hi01;
                *(uint32_t*)&g_Slo[(size_t)row * HID + gc]       = lo01;
                *(uint32_t*)&g_Shi[(size_t)(row + 8) * HID + gc] = hi23;
                *(uint32_t*)&g_Slo[(size_t)(row + 8) * HID + gc] = lo23;
            }
        }
    } else {
#pragma unroll
        for (int mt = 0; mt < 2; mt++) {
            int row = m0 + wm * 32 + mt * 16 + (lane >> 2);
#pragma unroll
            for (int nt = 0; nt < 4; nt++) {
                int col = n0 + wn * 32 + nt * 8 + (lane & 3) * 2;
                float bx = g_bias[col], by = g_bias[col + 1];
                float2 o0 = make_float2(acc[mt][nt][0] + bx, acc[mt][nt][1] + by);
                float2 o1 = make_float2(acc[mt][nt][2] + bx, acc[mt][nt][3] + by);
                *(float2*)&g_Y[(size_t)row * NF + col] = o0;
                *(float2*)&g_Y[(size_t)(row + 8) * NF + col] = o1;
            }
        }
    }
}

// ======================= K3: combine (BM=64, 128 thr, 3 CTA/SM) =======================
#define C_BUF 10240             // per A buffer: hi 5120 + lo 5120
#define C_BH  20480             // B hi plane: 256 rows * 80B
#define C_BL  (C_BH + 20480)
#define COMB_SMEM (C_BL + 20480)

__global__ void __launch_bounds__(128, 3) combine_kernel(float* __restrict__ out) {
    extern __shared__ char csm[];
    uint32_t sb = smem_u32(csm);
    __shared__ float s_msb[NA];
    int tid = threadIdx.x, lane = tid & 31, wid = tid >> 5;  // 4 warps
    int m0 = blockIdx.x * 64;
    if (tid < NA) s_msb[tid] = g_msb[tid];

    for (int i = tid; i < 1024; i += 128) {
        int row = i >> 2, ch = i & 3;
        cp16(sb + C_BH + row * 80 + ch * 16, g_w2h + row * 32 + ch * 8);
        cp16(sb + C_BL + row * 80 + ch * 16, g_w2l + row * 32 + ch * 8);
    }

    auto loadA = [&](int c, int buf) {
        int k0 = c * 32;
        uint32_t base = sb + buf * C_BUF;
#pragma unroll
        for (int i = tid; i < 256; i += 128) {
            int row = i >> 2, ch = i & 3;
            size_t src = (size_t)(m0 + row) * HID + k0 + ch * 8;
            cp16(base + row * 80 + ch * 16, g_Shi + src);
            cp16(base + 5120 + row * 80 + ch * 16, g_Slo + src);
        }
    };

    float acc[4][4];
#pragma unroll
    for (int nt = 0; nt < 4; nt++)
#pragma unroll
        for (int i = 0; i < 4; i++) acc[nt][i] = 0.f;

    loadA(0, 0);
    CP_COMMIT;
    for (int c = 0; c < 8; c++) {
        if (c + 1 < 8) { loadA(c + 1, (c + 1) & 1); CP_COMMIT; CP_WAIT1; }
        else           { CP_WAIT0; }
        __syncthreads();
        uint32_t abase = sb + (c & 1) * C_BUF;
#pragma unroll
        for (int ks = 0; ks < 32; ks += 16) {
            uint32_t ah[4], al[4], bh[2][4], bl[2][4];
            int arow = (lane & 7) + ((lane >> 3) & 1) * 8;
            int akk = ks + (lane >> 4) * 8;
            uint32_t ao = (wid * 16 + arow) * 80 + akk * 2;
            ldsm_x4(ah, abase + ao);
            ldsm_x4(al, abase + 5120 + ao);
            int bkg = c * 32 + ks + (lane & 7) + ((lane >> 3) & 1) * 8;
#pragma unroll
            for (int np = 0; np < 2; np++) {
                int bn = np * 16 + ((lane >> 4) & 1) * 8;
                uint32_t bo = bkg * 80 + bn * 2;
                ldsm_x4t(bh[np], sb + C_BH + bo);
                ldsm_x4t(bl[np], sb + C_BL + bo);
            }
#pragma unroll
            for (int nt = 0; nt < 4; nt++) {
                int np = nt >> 1, hf = nt & 1;
                mma16816(acc[nt], ah, &bh[np][hf * 2]);
                mma16816(acc[nt], al, &bh[np][hf * 2]);
                mma16816(acc[nt], ah, &bl[np][hf * 2]);
            }
        }
        __syncthreads();
    }

    int rbase = m0 + wid * 16 + (lane >> 2);
#pragma unroll
    for (int half = 0; half < 2; half++) {
        int row = rbase + half * 8;
        const float* Yr = g_Y + (size_t)row * NF;
        float qv[8], sc[8], mv[8];
#pragma unroll
        for (int nt = 0; nt < 4; nt++) {
            int col = nt * 8 + (lane & 3) * 2;
            float2 q2 = *(const float2*)&Yr[256 + col];
            float2 s2 = *(const float2*)&Yr[288 + col];
            qv[nt * 2] = q2.x; qv[nt * 2 + 1] = q2.y;
            sc[nt * 2] = s2.x; sc[nt * 2 + 1] = s2.y;
            mv[nt * 2]     = acc[nt][half * 2 + 0] + s_msb[col];
            mv[nt * 2 + 1] = acc[nt][half * 2 + 1] + s_msb[col + 1];
        }
        float mx = sc[0];
#pragma unroll
        for (int i = 1; i < 8; i++) mx = fmaxf(mx, sc[i]);
        mx = fmaxf(mx, __shfl_xor_sync(0xffffffffu, mx, 1));
        mx = fmaxf(mx, __shfl_xor_sync(0xffffffffu, mx, 2));
        float e[8], se = 0.f;
#pragma unroll
        for (int i = 0; i < 8; i++) { e[i] = __expf(sc[i] - mx); se += e[i]; }
        se += __shfl_xor_sync(0xffffffffu, se, 1);
        se += __shfl_xor_sync(0xffffffffu, se, 2);
        float inv = 1.f / se;
#pragma unroll
        for (int nt = 0; nt < 4; nt++) {
            int col = nt * 8 + (lane & 3) * 2;
            float2 o;
            o.x = qv[nt * 2]     + e[nt * 2]     * inv * mv[nt * 2];
            o.y = qv[nt * 2 + 1] + e[nt * 2 + 1] * inv * mv[nt * 2 + 1];
            *(float2*)&out[(size_t)row * NA + col] = o;
        }
    }
}

// ======================= launch =======================
extern "C" void kernel_launch(void* const* d_in, const int* in_sizes, int n_in,
                              void* d_out, int out_size) {
    const float* h   = (const float*)d_in[0];
    const float* act = (const float*)d_in[1];
    const float* qfw = (const float*)d_in[2];
    const float* qfb = (const float*)d_in[3];
    const float* w1  = (const float*)d_in[4];
    const float* b1  = (const float*)d_in[5];
    const float* w2  = (const float*)d_in[6];
    const float* b2  = (const float*)d_in[7];
    const float* kw  = (const float*)d_in[8];
    const float* kb  = (const float*)d_in[9];
    const float* qw  = (const float*)d_in[10];
    const float* qb  = (const float*)d_in[11];
    float* out = (float*)d_out;
    (void)in_sizes; (void)n_in; (void)out_size;

    cudaFuncSetAttribute(gemm_mma_kernel, cudaFuncAttributeMaxDynamicSharedMemorySize, GEMM_SMEM);
    cudaFuncSetAttribute(combine_kernel,  cudaFuncAttributeMaxDynamicSharedMemorySize, COMB_SMEM);

    prep_kernel<<<352 + APACK_HALF / 256, 256>>>(h, act, qfw, qfb, w1, b1, w2, b2, kw, kb, qw, qb);  // #0
    dim3 ggrid(NF / 64, NB / 128);
    gemm_mma_kernel<<<ggrid, 256, GEMM_SMEM>>>();                                                     // #1
    combine_kernel<<<NB / 64, 128, COMB_SMEM>>>(out);                                                 // #2
}